// round 14
// baseline (speedup 1.0000x reference)
#include <cuda_runtime.h>
#include <cuda_fp16.h>
#include <cstdint>

// ---------------------------------------------------------------------------
// Problem constants
// ---------------------------------------------------------------------------
#define BATCH   2
#define SEQ     2048
#define DMODEL  1024
#define DK      64
#define HPS     8
#define MROWS   (BATCH * SEQ)        // 4096

// Row permutation (per batch): even seq positions -> [0,1024), odd -> [1024,2048).
#define PERM(s) (((s) >> 1) + (((s) & 1) << 10))
// inverse: source seq for permuted row d (within batch)
#define IPERM(d) ((((d) & 1023) << 1) | ((d) >> 10))

// ---------------------------------------------------------------------------
// Scratch
// ---------------------------------------------------------------------------
__device__ __align__(16) __half g_Qh[MROWS * DMODEL];
__device__ __align__(16) __half g_Kh[MROWS * DMODEL];
__device__ __align__(16) __half g_Vh[MROWS * DMODEL];
__device__ __align__(16) __half g_ctxh[MROWS * DMODEL];
// scale-2 attention: unnormalized key-half partials (fp16) + row l-sums (fp32)
__device__ __align__(16) __half g_O2ph[2][BATCH * HPS * (SEQ / 2) * DK];
__device__ float g_l2[2][BATCH * HPS * (SEQ / 2)];
__device__ int g_ctr;
// half copies of weights only (inputs converted inside gemm_qkv)
__device__ __align__(16) __half g_wqh[DMODEL * DMODEL];
__device__ __align__(16) __half g_wkh[DMODEL * DMODEL];
__device__ __align__(16) __half g_wvh[DMODEL * DMODEL];
__device__ __align__(16) __half g_woh[DMODEL * DMODEL];

// ---------------------------------------------------------------------------
// Helpers
// ---------------------------------------------------------------------------
__device__ __forceinline__ uint32_t smem_u32(const void* p) {
    return (uint32_t)__cvta_generic_to_shared(p);
}
__device__ __forceinline__ void mma_f16(
    float& c0, float& c1, float& c2, float& c3,
    uint32_t a0, uint32_t a1, uint32_t a2, uint32_t a3,
    uint32_t b0, uint32_t b1)
{
    asm volatile(
        "mma.sync.aligned.m16n8k16.row.col.f32.f16.f16.f32 "
        "{%0,%1,%2,%3}, {%4,%5,%6,%7}, {%8,%9}, {%0,%1,%2,%3};"
        : "+f"(c0), "+f"(c1), "+f"(c2), "+f"(c3)
        : "r"(a0), "r"(a1), "r"(a2), "r"(a3), "r"(b0), "r"(b1));
}
#define LDSM_X4(r0, r1, r2, r3, addr) \
    asm volatile("ldmatrix.sync.aligned.m8n8.x4.shared.b16 {%0,%1,%2,%3}, [%4];" \
                 : "=r"(r0), "=r"(r1), "=r"(r2), "=r"(r3) : "r"(addr))
#define LDSM_X4T(r0, r1, r2, r3, addr) \
    asm volatile("ldmatrix.sync.aligned.m8n8.x4.trans.shared.b16 {%0,%1,%2,%3}, [%4];" \
                 : "=r"(r0), "=r"(r1), "=r"(r2), "=r"(r3) : "r"(addr))

__device__ __forceinline__ void cpa16(const void* sdst, const void* g) {
    uint32_t s = smem_u32(sdst);
    asm volatile("cp.async.cg.shared.global [%0], [%1], 16;" :: "r"(s), "l"(g));
}
__device__ __forceinline__ void cpa_commit() {
    asm volatile("cp.async.commit_group;");
}
template <int N>
__device__ __forceinline__ void cpa_wait() {
    asm volatile("cp.async.wait_group %0;" :: "n"(N));
}

// MUFU exp2 (off the FMA pipe).
__device__ __forceinline__ float ex2f(float y) {
    float r;
    asm("ex2.approx.f32 %0, %1;" : "=f"(r) : "f"(y));
    return r;
}

// ---------------------------------------------------------------------------
// Prepass: weights fp32 -> fp16 (24MB total). Inputs are converted inside
// gemm_qkv now. Resets the flash work counter.
// ---------------------------------------------------------------------------
__global__ __launch_bounds__(256) void prepass_w(
    const float* __restrict__ wq, const float* __restrict__ wk,
    const float* __restrict__ wv, const float* __restrict__ wo)
{
    if (blockIdx.x == 0 && threadIdx.x == 0) g_ctr = 0;
    size_t i4 = (size_t)blockIdx.x * 256 + threadIdx.x;   // 0..1048575
    size_t a = i4 >> 18;
    size_t off = (i4 & 262143u) << 2;
    const float* s = (a == 0) ? wq : (a == 1) ? wk : (a == 2) ? wv : wo;
    __half* d = (a == 0) ? g_wqh : (a == 1) ? g_wkh : (a == 2) ? g_wvh : g_woh;
    float4 x = *(const float4*)&s[off];
    __half2 h01 = __floats2half2_rn(x.x, x.y);
    __half2 h23 = __floats2half2_rn(x.z, x.w);
    uint2 u;
    u.x = *(uint32_t*)&h01;
    u.y = *(uint32_t*)&h23;
    *(uint2*)&d[off] = u;
}

// ---------------------------------------------------------------------------
// GEMM common layout: 128x256 tile, BK=32, 4 stages. A fp16 smem [128][40],
// B fp16 smem [32][264].
// ---------------------------------------------------------------------------
#define GBK 32
#define ASTR 40
#define BSTR 264
#define A_ST_BYTES (128 * ASTR * 2)
#define B_ST_BYTES (GBK * BSTR * 2)
#define A_TOT (4 * A_ST_BYTES)
#define GEMM_SMEM (A_TOT + 4 * B_ST_BYTES)

__device__ __forceinline__ void issueB256(
    char* dsm, const __half* __restrict__ W, int bcol, int st, int k0, int tid)
{
    char* Bs = dsm + A_TOT + st * B_ST_BYTES;
#pragma unroll
    for (int r = 0; r < 4; r++) {
        int c = tid + r * 256;
        int brw = c >> 5, bch = (c & 31) << 3;
        cpa16(Bs + brw * (BSTR * 2) + bch * 2,
              &W[(size_t)(k0 + brw) * DMODEL + bcol + bch]);
    }
}

// Compute inner loop body (shared by both GEMM kernels): consume stage st.
#define GEMM_COMPUTE_STAGE(dsm_, st_)                                          \
    do {                                                                       \
        const char* As_ = (dsm_) + (st_) * A_ST_BYTES;                         \
        const char* Bs_ = (dsm_) + A_TOT + (st_) * B_ST_BYTES;                 \
        _Pragma("unroll")                                                      \
        for (int kc = 0; kc < GBK; kc += 16) {                                 \
            uint32_t af[4][4];                                                 \
            _Pragma("unroll")                                                  \
            for (int i = 0; i < 4; i++) {                                      \
                uint32_t addr = smem_u32(As_ + (wm + 16 * i + a_row_l) * (ASTR * 2) \
                                              + (kc + a_k_l) * 2);             \
                LDSM_X4(af[i][0], af[i][1], af[i][2], af[i][3], addr);         \
            }                                                                  \
            uint32_t bf[8][2];                                                 \
            _Pragma("unroll")                                                  \
            for (int jp = 0; jp < 4; jp++) {                                   \
                uint32_t addr = smem_u32(Bs_ + (kc + b_row_l) * (BSTR * 2)     \
                                              + (wn + jp * 16 + b_col_l) * 2); \
                LDSM_X4T(bf[jp * 2][0], bf[jp * 2][1],                         \
                         bf[jp * 2 + 1][0], bf[jp * 2 + 1][1], addr);          \
            }                                                                  \
            _Pragma("unroll")                                                  \
            for (int i = 0; i < 4; i++)                                        \
                _Pragma("unroll")                                              \
                for (int j = 0; j < 8; j++)                                    \
                    mma_f16(c[i][j][0], c[i][j][1], c[i][j][2], c[i][j][3],    \
                            af[i][0], af[i][1], af[i][2], af[i][3],            \
                            bf[j][0], bf[j][1]);                               \
        }                                                                      \
    } while (0)

// ---------------------------------------------------------------------------
// gemm_qkv: A read as fp32 from the ORIGINAL inputs (inverse-permuted rows),
// converted fp32->fp16 in-register (LDG -> cvt -> STS), double-buffered regs.
// B via 4-stage cp.async from pre-converted fp16 weights.
// Grid (2, 48, 3): by<32 full row blocks cols 0-511; by>=32 even rows, 512+.
// ---------------------------------------------------------------------------
__global__ __launch_bounds__(256, 1) void gemm_qkv(
    const float* __restrict__ q, const float* __restrict__ k,
    const float* __restrict__ v,
    const float* __restrict__ bq, const float* __restrict__ bk,
    const float* __restrict__ bv)
{
    int z = blockIdx.z;
    const float* Af = (z == 0) ? q : (z == 1) ? k : v;
    const __half* W = (z == 0) ? g_wqh : (z == 1) ? g_wkh : g_wvh;
    const float* bias = (z == 0) ? bq : (z == 1) ? bk : bv;
    __half* C = (z == 0) ? g_Qh : (z == 1) ? g_Kh : g_Vh;

    int bcol, by;
    if (blockIdx.y < 32) { by = blockIdx.y; bcol = blockIdx.x * 256; }
    else {
        int rb = blockIdx.y - 32;
        by = (rb < 8) ? rb : rb + 8;
        bcol = 512 + blockIdx.x * 256;
    }
    const int brow = by * 128;

    extern __shared__ __align__(16) char dsm[];

    const int tid  = threadIdx.x;
    const int warp = tid >> 5;
    const int lane = tid & 31;
    const int g = lane >> 2;
    const int t = lane & 3;
    const int wm = (warp >> 2) * 64;
    const int wn = (warp & 3) * 64;

    // ---- A loader: one row per thread-pair, 16 floats each ----
    const int arow = tid >> 1;           // 0..127
    const int fh   = (tid & 1) * 16;     // float column base
    const int R  = brow + arow;
    const int bb = R >> 11, rq = R & 2047;
    const float* arowp = Af + (size_t)(bb * 2048 + IPERM(rq)) * DMODEL + fh;
    char* aout = dsm /* + stage offset */ + arow * (ASTR * 2) + fh * 2;

    float4 bufA[2][4];
    auto ldgA = [&](int buf, int k0) {
#pragma unroll
        for (int e = 0; e < 4; e++)
            bufA[buf][e] = *(const float4*)(arowp + k0 + e * 4);
    };
    auto stsA = [&](int buf, int st) {
        uint4 u0, u1;
        {
            __half2 p0 = __floats2half2_rn(bufA[buf][0].x, bufA[buf][0].y);
            __half2 p1 = __floats2half2_rn(bufA[buf][0].z, bufA[buf][0].w);
            __half2 p2 = __floats2half2_rn(bufA[buf][1].x, bufA[buf][1].y);
            __half2 p3 = __floats2half2_rn(bufA[buf][1].z, bufA[buf][1].w);
            u0 = make_uint4(*(uint32_t*)&p0, *(uint32_t*)&p1,
                            *(uint32_t*)&p2, *(uint32_t*)&p3);
            __half2 p4 = __floats2half2_rn(bufA[buf][2].x, bufA[buf][2].y);
            __half2 p5 = __floats2half2_rn(bufA[buf][2].z, bufA[buf][2].w);
            __half2 p6 = __floats2half2_rn(bufA[buf][3].x, bufA[buf][3].y);
            __half2 p7 = __floats2half2_rn(bufA[buf][3].z, bufA[buf][3].w);
            u1 = make_uint4(*(uint32_t*)&p4, *(uint32_t*)&p5,
                            *(uint32_t*)&p6, *(uint32_t*)&p7);
        }
        *(uint4*)(aout + st * A_ST_BYTES)      = u0;
        *(uint4*)(aout + st * A_ST_BYTES + 16) = u1;
    };

    float c[4][8][4];
#pragma unroll
    for (int i = 0; i < 4; i++)
#pragma unroll
        for (int j = 0; j < 8; j++)
#pragma unroll
            for (int r = 0; r < 4; r++) c[i][j][r] = 0.0f;

    // ---- prologue ----
    ldgA(0, 0);       stsA(0, 0);
    ldgA(0, GBK);     stsA(0, 1);
    issueB256(dsm, W, bcol, 0, 0, tid);        cpa_commit();
    issueB256(dsm, W, bcol, 1, GBK, tid);      cpa_commit();
    issueB256(dsm, W, bcol, 2, 2 * GBK, tid);  cpa_commit();
    ldgA(0, 2 * GBK);     // -> stage 2
    ldgA(1, 3 * GBK);     // -> stage 3

    const int a_row_l = lane & 15;
    const int a_k_l   = (lane >> 4) << 3;
    const int b_row_l = (lane & 7) + (((lane >> 3) & 1) << 3);
    const int b_col_l = (lane >> 4) << 3;

    const int NIT = DMODEL / GBK;   // 32
    for (int it = 0; it < NIT; it++) {
        const int st = it & 3;
        cpa_wait<2>();
        __syncthreads();
        if (it + 2 < NIT) stsA(it & 1, (it + 2) & 3);
        if (it + 3 < NIT) issueB256(dsm, W, bcol, (it + 3) & 3, (it + 3) * GBK, tid);
        cpa_commit();
        if (it + 4 < NIT) ldgA(it & 1, (it + 4) * GBK);

        GEMM_COMPUTE_STAGE(dsm, st);
    }

    // ---- epilogue (fp16 out) ----
    float bj[8][2];
#pragma unroll
    for (int j = 0; j < 8; j++) {
        int col = bcol + wn + 8 * j + 2 * t;
        bj[j][0] = bias[col];
        bj[j][1] = bias[col + 1];
    }
#pragma unroll
    for (int i = 0; i < 4; i++) {
        int row0 = brow + wm + 16 * i + g;
#pragma unroll
        for (int j = 0; j < 8; j++) {
            int col = bcol + wn + 8 * j + 2 * t;
            __half2 h0 = __floats2half2_rn(c[i][j][0] + bj[j][0], c[i][j][1] + bj[j][1]);
            __half2 h1 = __floats2half2_rn(c[i][j][2] + bj[j][0], c[i][j][3] + bj[j][1]);
            *(uint32_t*)&C[(size_t)row0 * DMODEL + col] = *(uint32_t*)&h0;
            *(uint32_t*)&C[(size_t)(row0 + 8) * DMODEL + col] = *(uint32_t*)&h1;
        }
    }
}

// ---------------------------------------------------------------------------
// gemm_out: both operands fp16 (ctx + w_o), 4-stage cp.async, fp32 out.
// ---------------------------------------------------------------------------
__device__ __forceinline__ void issueA256h(
    char* dsm, const __half* __restrict__ A, int brow, int st, int k0, int tid)
{
    char* As = dsm + st * A_ST_BYTES;
#pragma unroll
    for (int r = 0; r < 2; r++) {
        int c = tid + r * 256;
        int ar = c >> 2, ach = (c & 3) << 3;
        cpa16(As + ar * (ASTR * 2) + ach * 2,
              &A[(size_t)(brow + ar) * DMODEL + k0 + ach]);
    }
}

__global__ __launch_bounds__(256, 1) void gemm_out(
    const float* __restrict__ bo, float* __restrict__ out)
{
    const __half* A = g_ctxh;
    const __half* W = g_woh;
    const int brow = blockIdx.y * 128;
    const int bcol = blockIdx.x * 256;

    extern __shared__ __align__(16) char dsm[];

    const int tid  = threadIdx.x;
    const int warp = tid >> 5;
    const int lane = tid & 31;
    const int g = lane >> 2;
    const int t = lane & 3;
    const int wm = (warp >> 2) * 64;
    const int wn = (warp & 3) * 64;

    float c[4][8][4];
#pragma unroll
    for (int i = 0; i < 4; i++)
#pragma unroll
        for (int j = 0; j < 8; j++)
#pragma unroll
            for (int r = 0; r < 4; r++) c[i][j][r] = 0.0f;

    issueA256h(dsm, A, brow, 0, 0, tid);
    issueB256(dsm, W, bcol, 0, 0, tid);        cpa_commit();
    issueA256h(dsm, A, brow, 1, GBK, tid);
    issueB256(dsm, W, bcol, 1, GBK, tid);      cpa_commit();
    issueA256h(dsm, A, brow, 2, 2 * GBK, tid);
    issueB256(dsm, W, bcol, 2, 2 * GBK, tid);  cpa_commit();

    const int a_row_l = lane & 15;
    const int a_k_l   = (lane >> 4) << 3;
    const int b_row_l = (lane & 7) + (((lane >> 3) & 1) << 3);
    const int b_col_l = (lane >> 4) << 3;

    const int NIT = DMODEL / GBK;
    for (int it = 0; it < NIT; it++) {
        const int st = it & 3;
        cpa_wait<2>();
        __syncthreads();
        if (it + 3 < NIT) {
            issueA256h(dsm, A, brow, (it + 3) & 3, (it + 3) * GBK, tid);
            issueB256(dsm, W, bcol, (it + 3) & 3, (it + 3) * GBK, tid);
        }
        cpa_commit();

        GEMM_COMPUTE_STAGE(dsm, st);
    }

    float bj[8][2];
#pragma unroll
    for (int j = 0; j < 8; j++) {
        int col = bcol + wn + 8 * j + 2 * t;
        bj[j][0] = bo[col];
        bj[j][1] = bo[col + 1];
    }
#pragma unroll
    for (int i = 0; i < 4; i++) {
        int row0 = brow + wm + 16 * i + g;
#pragma unroll
        for (int j = 0; j < 8; j++) {
            int col = bcol + wn + 8 * j + 2 * t;
            float2 v0 = make_float2(c[i][j][0] + bj[j][0], c[i][j][1] + bj[j][1]);
            float2 v1 = make_float2(c[i][j][2] + bj[j][0], c[i][j][3] + bj[j][1]);
            *(float2*)&out[(size_t)row0 * DMODEL + col] = v0;
            *(float2*)&out[(size_t)(row0 + 8) * DMODEL + col] = v1;
        }
    }
}

// ---------------------------------------------------------------------------
// Persistent FP16 flash attention. 296 CTAs x 256 thr, atomic work queue.
// Items 0..255:   scale1, 128q x 2048k (64 tiles); normalized, -> g_ctxh.
// Items 256..511: scale2, 128q x 512k key-half (16 tiles); UNNORMALIZED
//                 fp16 partial O + fp32 per-row l to g_O2ph/g_l2.
// ---------------------------------------------------------------------------
#define FKT 32
#define KVSTR 72
#define NITEMS 512

__global__ __launch_bounds__(256, 2) void flash_tc()
{
    __shared__ __align__(16) __half Ks[3][FKT][KVSTR];
    __shared__ __align__(16) __half Vs[3][FKT][KVSTR];
    __shared__ int s_item;

    const int tid  = threadIdx.x;
    const int warp = tid >> 5;
    const int lane = tid & 31;
    const int g = lane >> 2;
    const int t = lane & 3;
    const int wr = warp * 16;
    const int lrow = tid >> 3;
    const int lch  = (tid & 7) << 3;

    const int kn_row_l = (lane & 7) + (((lane >> 4) & 1) << 3);
    const int kn_col_l = ((lane >> 3) & 1) << 3;
    const int v_row_l  = (lane & 7) + (((lane >> 3) & 1) << 3);
    const int v_col_l  = (lane >> 4) << 3;
    const float qs = 0.125f * 1.4426950408889634f;

    for (;;) {
        if (tid == 0) s_item = atomicAdd(&g_ctr, 1);
        __syncthreads();
        const int item = s_item;
        __syncthreads();
        if (item >= NITEMS) break;

        int f, head_off, qblk, bz, h, kh, ntiles;
        if (item < 256) {
            f = 1; head_off = 0; kh = 0; ntiles = 64;
            bz = item >> 7; h = (item >> 4) & 7; qblk = item & 15;
        } else {
            int j = item - 256;
            f = 2; head_off = HPS; ntiles = 16;
            kh = j & 1;
            int jj = j >> 1;
            bz = jj >> 6; h = (jj >> 3) & 7; qblk = jj & 7;
        }
        const int col = (head_off + h) * DK;
        const int q0  = qblk * 128;
        const int tbase = kh * 16;
        const size_t seqbase = (size_t)bz * SEQ;

        // ---- Q fragments (permuted rows) ----
        uint32_t qf[4][4];
        {
            int sq0 = (q0 + wr + g) * f;
            int sq1 = sq0 + 8 * f;
            size_t r0 = (seqbase + PERM(sq0)) * DMODEL + col;
            size_t r1 = (seqbase + PERM(sq1)) * DMODEL + col;
#pragma unroll
            for (int kc = 0; kc < 4; kc++) {
                qf[kc][0] = *(const uint32_t*)&g_Qh[r0 + kc * 16 + 2 * t];
                qf[kc][1] = *(const uint32_t*)&g_Qh[r1 + kc * 16 + 2 * t];
                qf[kc][2] = *(const uint32_t*)&g_Qh[r0 + kc * 16 + 2 * t + 8];
                qf[kc][3] = *(const uint32_t*)&g_Qh[r1 + kc * 16 + 2 * t + 8];
            }
        }

        float oacc[8][4];
#pragma unroll
        for (int j = 0; j < 8; j++)
#pragma unroll
            for (int r = 0; r < 4; r++) oacc[j][r] = 0.0f;
        float l0 = 0.0f, l1 = 0.0f;

        auto issue = [&](int tile, int buf) {
            int sk = ((tbase + tile) * FKT + lrow) * f;
            size_t src = (seqbase + PERM(sk)) * DMODEL + col + lch;
            cpa16(&Ks[buf][lrow][lch], &g_Kh[src]);
            cpa16(&Vs[buf][lrow][lch], &g_Vh[src]);
        };

        issue(0, 0);
        cpa_commit();
        issue(1, 1);
        cpa_commit();

        int st = 0;
        for (int kt = 0; kt < ntiles; kt++) {
            cpa_wait<1>();
            __syncthreads();
            if (kt + 2 < ntiles) {
                int st2 = st + 2; if (st2 >= 3) st2 -= 3;
                issue(kt + 2, st2);
            }
            cpa_commit();

            // ---- S = Q K^T ----
            float sacc[4][4];
#pragma unroll
            for (int j = 0; j < 4; j++)
#pragma unroll
                for (int r = 0; r < 4; r++) sacc[j][r] = 0.0f;
#pragma unroll
            for (int kc = 0; kc < 4; kc++) {
                uint32_t bf[4][2];
#pragma unroll
                for (int jp = 0; jp < 2; jp++) {
                    uint32_t addr = smem_u32(&Ks[st][jp * 16 + kn_row_l][kc * 16 + kn_col_l]);
                    LDSM_X4(bf[jp * 2][0], bf[jp * 2][1],
                            bf[jp * 2 + 1][0], bf[jp * 2 + 1][1], addr);
                }
#pragma unroll
                for (int j = 0; j < 4; j++)
                    mma_f16(sacc[j][0], sacc[j][1], sacc[j][2], sacc[j][3],
                            qf[kc][0], qf[kc][1], qf[kc][2], qf[kc][3],
                            bf[j][0], bf[j][1]);
            }

            // ---- P = exp2(S*qs) via MUFU, straight into A fragments ----
            uint32_t pa[4][2];
#pragma unroll
            for (int j = 0; j < 4; j++) {
                float p00 = ex2f(sacc[j][0] * qs);
                float p01 = ex2f(sacc[j][1] * qs);
                float p10 = ex2f(sacc[j][2] * qs);
                float p11 = ex2f(sacc[j][3] * qs);
                l0 += p00 + p01;
                l1 += p10 + p11;
                __half2 h0 = __floats2half2_rn(p00, p01);
                __half2 h1 = __floats2half2_rn(p10, p11);
                pa[j][0] = *(uint32_t*)&h0;
                pa[j][1] = *(uint32_t*)&h1;
            }

            // ---- O += P V ----
#pragma unroll
            for (int c2 = 0; c2 < 2; c2++) {
                uint32_t a0 = pa[2 * c2][0], a1 = pa[2 * c2][1];
                uint32_t a2 = pa[2 * c2 + 1][0], a3 = pa[2 * c2 + 1][1];
#pragma unroll
                for (int jp = 0; jp < 4; jp++) {
                    uint32_t bf0, bf1, bf2, bf3;
                    uint32_t addr = smem_u32(&Vs[st][c2 * 16 + v_row_l][jp * 16 + v_col_l]);
                    LDSM_X4T(bf0, bf1, bf2, bf3, addr);
                    mma_f16(oacc[2 * jp][0], oacc[2 * jp][1], oacc[2 * jp][2], oacc[2 * jp][3],
                            a0, a1, a2, a3, bf0, bf1);
                    mma_f16(oacc[2 * jp + 1][0], oacc[2 * jp + 1][1],
                            oacc[2 * jp + 1][2], oacc[2 * jp + 1][3],
                            a0, a1, a2, a3, bf2, bf3);
                }
            }
            if (++st >= 3) st = 0;
        }

        // ---- finalize ----
        l0 += __shfl_xor_sync(0xffffffff, l0, 1);
        l0 += __shfl_xor_sync(0xffffffff, l0, 2);
        l1 += __shfl_xor_sync(0xffffffff, l1, 1);
        l1 += __shfl_xor_sync(0xffffffff, l1, 2);

        int row0 = q0 + wr + g;
        if (f == 1) {
            float inv0 = 1.0f / l0;
            float inv1 = 1.0f / l1;
            size_t b0 = (seqbase + row0) * DMODEL + col;
            size_t b1 = (seqbase + row0 + 8) * DMODEL + col;
#pragma unroll
            for (int j = 0; j < 8; j++) {
                int c2 = j * 8 + 2 * t;
                __half2 h0 = __floats2half2_rn(oacc[j][0] * inv0, oacc[j][1] * inv0);
                __half2 h1 = __floats2half2_rn(oacc[j][2] * inv1, oacc[j][3] * inv1);
                *(uint32_t*)&g_ctxh[b0 + c2] = *(uint32_t*)&h0;
                *(uint32_t*)&g_ctxh[b1 + c2] = *(uint32_t*)&h1;
            }
        } else {
            // unnormalized fp16 key-half partial + fp32 l-sums
            size_t base = ((size_t)(bz * HPS + h)) * (SEQ / 2);
            __half* Op = g_O2ph[kh];
#pragma unroll
            for (int j = 0; j < 8; j++) {
                int c2 = j * 8 + 2 * t;
                __half2 h0 = __floats2half2_rn(oacc[j][0], oacc[j][1]);
                __half2 h1 = __floats2half2_rn(oacc[j][2], oacc[j][3]);
                *(uint32_t*)&Op[(base + row0) * DK + c2] = *(uint32_t*)&h0;
                *(uint32_t*)&Op[(base + row0 + 8) * DK + c2] = *(uint32_t*)&h1;
            }
            if (t == 0) {
                g_l2[kh][base + row0]     = l0;
                g_l2[kh][base + row0 + 8] = l1;
            }
        }
    }
}

// ---------------------------------------------------------------------------
// Combine scale-2 key-half partials + upsample into ctx heads 8-15.
// O(i) = (P0(i)+P1(i)) / (l0(i)+l1(i)); then linear interp.
// ---------------------------------------------------------------------------
__global__ __launch_bounds__(256) void upsample_ctx()
{
    int idx = blockIdx.x * 256 + threadIdx.x;
    int d  = (idx & 15) * 4;
    int hh = (idx >> 4) & 7;
    int s  = (idx >> 7) & 2047;
    int b  = idx >> 18;

    const int L = SEQ / 2;
    float coord = (s + 0.5f) * 0.5f - 0.5f;
    coord = fmaxf(coord, 0.0f);
    int i0 = min((int)floorf(coord), L - 1);
    int i1 = min(i0 + 1, L - 1);
    float w = coord - (float)i0;

    size_t base = ((size_t)(b * HPS + hh)) * L;
    float linv0 = 1.0f / (g_l2[0][base + i0] + g_l2[1][base + i0]);
    float linv1 = 1.0f / (g_l2[0][base + i1] + g_l2[1][base + i1]);

    uint2 ua0 = *(const uint2*)&g_O2ph[0][(base + i0) * DK + d];
    uint2 ub0 = *(const uint2*)&g_O2ph[1][(base + i0) * DK + d];
    uint2 ua1 = *(const uint2*)&g_O2ph[0][(base + i1) * DK + d];
    uint2 ub1 = *(const uint2*)&g_O2ph[1][(base + i1) * DK + d];

    float2 a0l = __half22float2(*(__half2*)&ua0.x), a0h = __half22float2(*(__half2*)&ua0.y);
    float2 b0l = __half22float2(*(__half2*)&ub0.x), b0h = __half22float2(*(__half2*)&ub0.y);
    float2 a1l = __half22float2(*(__half2*)&ua1.x), a1h = __half22float2(*(__half2*)&ua1.y);
    float2 b1l = __half22float2(*(__half2*)&ub1.x), b1h = __half22float2(*(__half2*)&ub1.y);

    float v0x = (a0l.x + b0l.x) * linv0, v0y = (a0l.y + b0l.y) * linv0;
    float v0z = (a0h.x + b0h.x) * linv0, v0w = (a0h.y + b0h.y) * linv0;
    float v1x = (a1l.x + b1l.x) * linv1, v1y = (a1l.y + b1l.y) * linv1;
    float v1z = (a1h.x + b1h.x) * linv1, v1w = (a1h.y + b1h.y) * linv1;

    float x0 = v0x + (v1x - v0x) * w;
    float x1 = v0y + (v1y - v0y) * w;
    float x2 = v0z + (v1z - v0z) * w;
    float x3 = v0w + (v1w - v0w) * w;

    __half2 h01 = __floats2half2_rn(x0, x1);
    __half2 h23 = __floats2half2_rn(x2, x3);
    uint2 u;
    u.x = *(uint32_t*)&h01;
    u.y = *(uint32_t*)&h23;
    *(uint2*)&g_ctxh[((size_t)(b * SEQ + s)) * DMODEL + 512 + hh * DK + d] = u;
}

// ---------------------------------------------------------------------------
// kernel_launch
// ---------------------------------------------------------------------------
extern "C" void kernel_launch(void* const* d_in, const int* in_sizes, int n_in,
                              void* d_out, int out_size)
{
    const float* query = (const float*)d_in[0];
    const float* key   = (const float*)d_in[1];
    const float* value = (const float*)d_in[2];
    const float* w_q   = (const float*)d_in[3];
    const float* b_q   = (const float*)d_in[4];
    const float* w_k   = (const float*)d_in[5];
    const float* b_k   = (const float*)d_in[6];
    const float* w_v   = (const float*)d_in[7];
    const float* b_v   = (const float*)d_in[8];
    const float* w_o   = (const float*)d_in[9];
    const float* b_o   = (const float*)d_in[10];
    float* out = (float*)d_out;

    static int attr_done = 0;
    if (!attr_done) {
        cudaFuncSetAttribute(gemm_qkv, cudaFuncAttributeMaxDynamicSharedMemorySize, GEMM_SMEM);
        cudaFuncSetAttribute(gemm_out, cudaFuncAttributeMaxDynamicSharedMemorySize, GEMM_SMEM);
        attr_done = 1;
    }

    prepass_w<<<4096, 256>>>(w_q, w_k, w_v, w_o);

    gemm_qkv<<<dim3(2, 48, 3), 256, GEMM_SMEM>>>(query, key, value, b_q, b_k, b_v);

    flash_tc<<<296, 256>>>();

    upsample_ctx<<<2048, 256>>>();

    gemm_out<<<dim3(4, 32), 256, GEMM_SMEM>>>(b_o, out);
}

// round 15
// speedup vs baseline: 1.0672x; 1.0672x over previous
#include <cuda_runtime.h>
#include <cuda_fp16.h>
#include <cstdint>

// ---------------------------------------------------------------------------
// Problem constants
// ---------------------------------------------------------------------------
#define BATCH   2
#define SEQ     2048
#define DMODEL  1024
#define DK      64
#define HPS     8
#define MROWS   (BATCH * SEQ)        // 4096

// Row permutation (per batch): even seq positions -> [0,1024), odd -> [1024,2048).
#define PERM(s) (((s) >> 1) + (((s) & 1) << 10))

// ---------------------------------------------------------------------------
// Scratch
// ---------------------------------------------------------------------------
__device__ __align__(16) __half g_Qh[MROWS * DMODEL];
__device__ __align__(16) __half g_Kh[MROWS * DMODEL];
__device__ __align__(16) __half g_Vh[MROWS * DMODEL];
__device__ __align__(16) __half g_ctxh[MROWS * DMODEL];
// scale-2 attention: unnormalized key-half partials (fp16) + row l-sums (fp32)
__device__ __align__(16) __half g_O2ph[2][BATCH * HPS * (SEQ / 2) * DK];
__device__ float g_l2[2][BATCH * HPS * (SEQ / 2)];
__device__ int g_ctr;
// half copies of inputs (row-permuted) and weights
__device__ __align__(16) __half g_qh[MROWS * DMODEL];
__device__ __align__(16) __half g_kh[MROWS * DMODEL];
__device__ __align__(16) __half g_vh[MROWS * DMODEL];
__device__ __align__(16) __half g_wqh[DMODEL * DMODEL];
__device__ __align__(16) __half g_wkh[DMODEL * DMODEL];
__device__ __align__(16) __half g_wvh[DMODEL * DMODEL];
__device__ __align__(16) __half g_woh[DMODEL * DMODEL];

// ---------------------------------------------------------------------------
// Helpers
// ---------------------------------------------------------------------------
__device__ __forceinline__ uint32_t smem_u32(const void* p) {
    return (uint32_t)__cvta_generic_to_shared(p);
}
__device__ __forceinline__ void mma_f16(
    float& c0, float& c1, float& c2, float& c3,
    uint32_t a0, uint32_t a1, uint32_t a2, uint32_t a3,
    uint32_t b0, uint32_t b1)
{
    asm volatile(
        "mma.sync.aligned.m16n8k16.row.col.f32.f16.f16.f32 "
        "{%0,%1,%2,%3}, {%4,%5,%6,%7}, {%8,%9}, {%0,%1,%2,%3};"
        : "+f"(c0), "+f"(c1), "+f"(c2), "+f"(c3)
        : "r"(a0), "r"(a1), "r"(a2), "r"(a3), "r"(b0), "r"(b1));
}
#define LDSM_X4(r0, r1, r2, r3, addr) \
    asm volatile("ldmatrix.sync.aligned.m8n8.x4.shared.b16 {%0,%1,%2,%3}, [%4];" \
                 : "=r"(r0), "=r"(r1), "=r"(r2), "=r"(r3) : "r"(addr))
#define LDSM_X4T(r0, r1, r2, r3, addr) \
    asm volatile("ldmatrix.sync.aligned.m8n8.x4.trans.shared.b16 {%0,%1,%2,%3}, [%4];" \
                 : "=r"(r0), "=r"(r1), "=r"(r2), "=r"(r3) : "r"(addr))

__device__ __forceinline__ void cpa16(const void* sdst, const void* g) {
    uint32_t s = smem_u32(sdst);
    asm volatile("cp.async.cg.shared.global [%0], [%1], 16;" :: "r"(s), "l"(g));
}
__device__ __forceinline__ void cpa_commit() {
    asm volatile("cp.async.commit_group;");
}
template <int N>
__device__ __forceinline__ void cpa_wait() {
    asm volatile("cp.async.wait_group %0;" :: "n"(N));
}

// MUFU exp2 (off the FMA pipe).
__device__ __forceinline__ float ex2f(float y) {
    float r;
    asm("ex2.approx.f32 %0, %1;" : "=f"(r) : "f"(y));
    return r;
}

// ---------------------------------------------------------------------------
// Prepass: fp32 -> fp16; inputs row-permuted, weights plain. 2 float4/thread.
// Grid = PRE_HALF/256 = 14336 blocks. Resets the flash work counter.
// ---------------------------------------------------------------------------
#define PRE_TOT (7u * 1048576u)      // total float4s (3 inputs + 4 weights)
#define PRE_HALF (PRE_TOT / 2)       // 3670016

__global__ __launch_bounds__(256) void prepass(
    const float* __restrict__ q, const float* __restrict__ k,
    const float* __restrict__ v,
    const float* __restrict__ wq, const float* __restrict__ wk,
    const float* __restrict__ wv, const float* __restrict__ wo)
{
    if (blockIdx.x == 0 && threadIdx.x == 0) g_ctr = 0;
    size_t gid = (size_t)blockIdx.x * 256 + threadIdx.x;
#pragma unroll
    for (int rep = 0; rep < 2; rep++) {
        size_t i4 = gid + (size_t)rep * PRE_HALF;
        const float* s; __half* d; size_t soff, doff;
        if (i4 < 3u * 1048576u) {
            size_t a = i4 >> 20;
            soff = (i4 & 1048575u) << 2;
            int row = (int)(soff >> 10);
            int col = (int)(soff & 1023);
            int b   = row >> 11;
            int sq  = row & 2047;
            doff = ((size_t)(b << 11) + PERM(sq)) * 1024 + col;
            s = (a == 0) ? q : (a == 1) ? k : v;
            d = (a == 0) ? g_qh : (a == 1) ? g_kh : g_vh;
        } else {
            size_t j = i4 - 3u * 1048576u;
            size_t a = j >> 18;
            soff = (j & 262143u) << 2;
            doff = soff;
            s = (a == 0) ? wq : (a == 1) ? wk : (a == 2) ? wv : wo;
            d = (a == 0) ? g_wqh : (a == 1) ? g_wkh : (a == 2) ? g_wvh : g_woh;
        }
        float4 x = *(const float4*)&s[soff];
        __half2 h01 = __floats2half2_rn(x.x, x.y);
        __half2 h23 = __floats2half2_rn(x.z, x.w);
        uint2 u;
        u.x = *(uint32_t*)&h01;
        u.y = *(uint32_t*)&h23;
        *(uint2*)&d[doff] = u;
    }
}

// ---------------------------------------------------------------------------
// FP16 tensor-core GEMM, 128x256 tile, BK=32, 4-stage cp.async, 256 thr
// (8 warps, 2m x 4n, warp tile 64x64). 1 CTA/SM; dynamic smem 106KB.
// (All operands staged via cp.async — NO register-transit loads; the R14
// fused LDG->cvt->STS loader exposed full gmem latency per iter and cost
// +25us in gemm_qkv.)
// ---------------------------------------------------------------------------
#define GBK 32
#define ASTR 40
#define BSTR 264
#define A_ST_BYTES (128 * ASTR * 2)
#define B_ST_BYTES (GBK * BSTR * 2)
#define A_TOT (4 * A_ST_BYTES)
#define GEMM_SMEM (A_TOT + 4 * B_ST_BYTES)

__device__ __forceinline__ void gemm_issue256(
    char* dsm, const __half* __restrict__ A, const __half* __restrict__ W,
    int brow, int bcol, int st, int k0, int tid)
{
    char* As = dsm + st * A_ST_BYTES;
    char* Bs = dsm + A_TOT + st * B_ST_BYTES;
#pragma unroll
    for (int r = 0; r < 2; r++) {
        int c = tid + r * 256;
        int arow = c >> 2, ach = (c & 3) << 3;
        cpa16(As + arow * (ASTR * 2) + ach * 2,
              &A[(size_t)(brow + arow) * DMODEL + k0 + ach]);
    }
#pragma unroll
    for (int r = 0; r < 4; r++) {
        int c = tid + r * 256;
        int brw = c >> 5, bch = (c & 31) << 3;
        cpa16(Bs + brw * (BSTR * 2) + bch * 2,
              &W[(size_t)(k0 + brw) * DMODEL + bcol + bch]);
    }
}

__device__ __forceinline__ void gemm_tile256(
    const __half* __restrict__ A, const __half* __restrict__ W,
    const float* __restrict__ bias, float* __restrict__ Cf,
    __half* __restrict__ Ch, int brow, int bcol)
{
    extern __shared__ __align__(16) char dsm[];

    const int tid  = threadIdx.x;
    const int warp = tid >> 5;
    const int lane = tid & 31;
    const int g = lane >> 2;
    const int t = lane & 3;
    const int wm = (warp >> 2) * 64;
    const int wn = (warp & 3) * 64;

    float c[4][8][4];
#pragma unroll
    for (int i = 0; i < 4; i++)
#pragma unroll
        for (int j = 0; j < 8; j++)
#pragma unroll
            for (int r = 0; r < 4; r++) c[i][j][r] = 0.0f;

    gemm_issue256(dsm, A, W, brow, bcol, 0, 0, tid);
    cpa_commit();
    gemm_issue256(dsm, A, W, brow, bcol, 1, GBK, tid);
    cpa_commit();
    gemm_issue256(dsm, A, W, brow, bcol, 2, 2 * GBK, tid);
    cpa_commit();

    const int a_row_l = lane & 15;
    const int a_k_l   = (lane >> 4) << 3;
    const int b_row_l = (lane & 7) + (((lane >> 3) & 1) << 3);
    const int b_col_l = (lane >> 4) << 3;

    const int NIT = DMODEL / GBK;
    for (int it = 0; it < NIT; it++) {
        const int st = it & 3;
        cpa_wait<2>();
        __syncthreads();
        if (it + 3 < NIT)
            gemm_issue256(dsm, A, W, brow, bcol, (it + 3) & 3, (it + 3) * GBK, tid);
        cpa_commit();

        const char* As = dsm + st * A_ST_BYTES;
        const char* Bs = dsm + A_TOT + st * B_ST_BYTES;
#pragma unroll
        for (int kc = 0; kc < GBK; kc += 16) {
            uint32_t af[4][4];
#pragma unroll
            for (int i = 0; i < 4; i++) {
                uint32_t addr = smem_u32(As + (wm + 16 * i + a_row_l) * (ASTR * 2)
                                            + (kc + a_k_l) * 2);
                LDSM_X4(af[i][0], af[i][1], af[i][2], af[i][3], addr);
            }
            uint32_t bf[8][2];
#pragma unroll
            for (int jp = 0; jp < 4; jp++) {
                uint32_t addr = smem_u32(Bs + (kc + b_row_l) * (BSTR * 2)
                                            + (wn + jp * 16 + b_col_l) * 2);
                LDSM_X4T(bf[jp * 2][0], bf[jp * 2][1],
                         bf[jp * 2 + 1][0], bf[jp * 2 + 1][1], addr);
            }
#pragma unroll
            for (int i = 0; i < 4; i++)
#pragma unroll
                for (int j = 0; j < 8; j++)
                    mma_f16(c[i][j][0], c[i][j][1], c[i][j][2], c[i][j][3],
                            af[i][0], af[i][1], af[i][2], af[i][3],
                            bf[j][0], bf[j][1]);
        }
    }

    float bj[8][2];
#pragma unroll
    for (int j = 0; j < 8; j++) {
        int col = bcol + wn + 8 * j + 2 * t;
        bj[j][0] = bias[col];
        bj[j][1] = bias[col + 1];
    }
#pragma unroll
    for (int i = 0; i < 4; i++) {
        int row0 = brow + wm + 16 * i + g;
#pragma unroll
        for (int j = 0; j < 8; j++) {
            int col = bcol + wn + 8 * j + 2 * t;
            float2 v0 = make_float2(c[i][j][0] + bj[j][0], c[i][j][1] + bj[j][1]);
            float2 v1 = make_float2(c[i][j][2] + bj[j][0], c[i][j][3] + bj[j][1]);
            if (Ch) {
                __half2 h0 = __floats2half2_rn(v0.x, v0.y);
                __half2 h1 = __floats2half2_rn(v1.x, v1.y);
                *(uint32_t*)&Ch[(size_t)row0 * DMODEL + col] = *(uint32_t*)&h0;
                *(uint32_t*)&Ch[(size_t)(row0 + 8) * DMODEL + col] = *(uint32_t*)&h1;
            } else {
                *(float2*)&Cf[(size_t)row0 * DMODEL + col] = v0;
                *(float2*)&Cf[(size_t)(row0 + 8) * DMODEL + col] = v1;
            }
        }
    }
}

__global__ __launch_bounds__(256, 1) void gemm_qkv(
    const float* __restrict__ bq, const float* __restrict__ bk,
    const float* __restrict__ bv)
{
    int z = blockIdx.z;
    const __half* A = (z == 0) ? g_qh : (z == 1) ? g_kh : g_vh;
    const __half* W = (z == 0) ? g_wqh : (z == 1) ? g_wkh : g_wvh;
    const float* b = (z == 0) ? bq : (z == 1) ? bk : bv;
    __half* C = (z == 0) ? g_Qh : (z == 1) ? g_Kh : g_Vh;

    int bcol, by;
    if (blockIdx.y < 32) { by = blockIdx.y; bcol = blockIdx.x * 256; }
    else {
        int rb = blockIdx.y - 32;
        by = (rb < 8) ? rb : rb + 8;
        bcol = 512 + blockIdx.x * 256;
    }
    gemm_tile256(A, W, b, nullptr, C, by * 128, bcol);
}

__global__ __launch_bounds__(256, 1) void gemm_out(
    const float* __restrict__ bo, float* __restrict__ out)
{
    gemm_tile256(g_ctxh, g_woh, bo, out, nullptr,
                 blockIdx.y * 128, blockIdx.x * 256);
}

// ---------------------------------------------------------------------------
// Persistent FP16 flash attention. 296 CTAs x 256 thr, atomic work queue.
// Items 0..255:   scale1, 128q x 2048k (64 tiles); normalized, -> g_ctxh.
// Items 256..511: scale2, 128q x 512k key-half (16 tiles); UNNORMALIZED
//                 fp16 partial O + fp32 per-row l to g_O2ph/g_l2.
// ---------------------------------------------------------------------------
#define FKT 32
#define KVSTR 72
#define NITEMS 512

__global__ __launch_bounds__(256, 2) void flash_tc()
{
    __shared__ __align__(16) __half Ks[3][FKT][KVSTR];
    __shared__ __align__(16) __half Vs[3][FKT][KVSTR];
    __shared__ int s_item;

    const int tid  = threadIdx.x;
    const int warp = tid >> 5;
    const int lane = tid & 31;
    const int g = lane >> 2;
    const int t = lane & 3;
    const int wr = warp * 16;
    const int lrow = tid >> 3;
    const int lch  = (tid & 7) << 3;

    const int kn_row_l = (lane & 7) + (((lane >> 4) & 1) << 3);
    const int kn_col_l = ((lane >> 3) & 1) << 3;
    const int v_row_l  = (lane & 7) + (((lane >> 3) & 1) << 3);
    const int v_col_l  = (lane >> 4) << 3;
    const float qs = 0.125f * 1.4426950408889634f;

    for (;;) {
        if (tid == 0) s_item = atomicAdd(&g_ctr, 1);
        __syncthreads();
        const int item = s_item;
        __syncthreads();
        if (item >= NITEMS) break;

        int f, head_off, qblk, bz, h, kh, ntiles;
        if (item < 256) {
            f = 1; head_off = 0; kh = 0; ntiles = 64;
            bz = item >> 7; h = (item >> 4) & 7; qblk = item & 15;
        } else {
            int j = item - 256;
            f = 2; head_off = HPS; ntiles = 16;
            kh = j & 1;
            int jj = j >> 1;
            bz = jj >> 6; h = (jj >> 3) & 7; qblk = jj & 7;
        }
        const int col = (head_off + h) * DK;
        const int q0  = qblk * 128;
        const int tbase = kh * 16;
        const size_t seqbase = (size_t)bz * SEQ;

        // ---- Q fragments (permuted rows) ----
        uint32_t qf[4][4];
        {
            int sq0 = (q0 + wr + g) * f;
            int sq1 = sq0 + 8 * f;
            size_t r0 = (seqbase + PERM(sq0)) * DMODEL + col;
            size_t r1 = (seqbase + PERM(sq1)) * DMODEL + col;
#pragma unroll
            for (int kc = 0; kc < 4; kc++) {
                qf[kc][0] = *(const uint32_t*)&g_Qh[r0 + kc * 16 + 2 * t];
                qf[kc][1] = *(const uint32_t*)&g_Qh[r1 + kc * 16 + 2 * t];
                qf[kc][2] = *(const uint32_t*)&g_Qh[r0 + kc * 16 + 2 * t + 8];
                qf[kc][3] = *(const uint32_t*)&g_Qh[r1 + kc * 16 + 2 * t + 8];
            }
        }

        float oacc[8][4];
#pragma unroll
        for (int j = 0; j < 8; j++)
#pragma unroll
            for (int r = 0; r < 4; r++) oacc[j][r] = 0.0f;
        float l0 = 0.0f, l1 = 0.0f;

        auto issue = [&](int tile, int buf) {
            int sk = ((tbase + tile) * FKT + lrow) * f;
            size_t src = (seqbase + PERM(sk)) * DMODEL + col + lch;
            cpa16(&Ks[buf][lrow][lch], &g_Kh[src]);
            cpa16(&Vs[buf][lrow][lch], &g_Vh[src]);
        };

        issue(0, 0);
        cpa_commit();
        issue(1, 1);
        cpa_commit();

        int st = 0;
        for (int kt = 0; kt < ntiles; kt++) {
            cpa_wait<1>();
            __syncthreads();
            if (kt + 2 < ntiles) {
                int st2 = st + 2; if (st2 >= 3) st2 -= 3;
                issue(kt + 2, st2);
            }
            cpa_commit();

            // ---- S = Q K^T ----
            float sacc[4][4];
#pragma unroll
            for (int j = 0; j < 4; j++)
#pragma unroll
                for (int r = 0; r < 4; r++) sacc[j][r] = 0.0f;
#pragma unroll
            for (int kc = 0; kc < 4; kc++) {
                uint32_t bf[4][2];
#pragma unroll
                for (int jp = 0; jp < 2; jp++) {
                    uint32_t addr = smem_u32(&Ks[st][jp * 16 + kn_row_l][kc * 16 + kn_col_l]);
                    LDSM_X4(bf[jp * 2][0], bf[jp * 2][1],
                            bf[jp * 2 + 1][0], bf[jp * 2 + 1][1], addr);
                }
#pragma unroll
                for (int j = 0; j < 4; j++)
                    mma_f16(sacc[j][0], sacc[j][1], sacc[j][2], sacc[j][3],
                            qf[kc][0], qf[kc][1], qf[kc][2], qf[kc][3],
                            bf[j][0], bf[j][1]);
            }

            // ---- P = exp2(S*qs) via MUFU, straight into A fragments ----
            uint32_t pa[4][2];
#pragma unroll
            for (int j = 0; j < 4; j++) {
                float p00 = ex2f(sacc[j][0] * qs);
                float p01 = ex2f(sacc[j][1] * qs);
                float p10 = ex2f(sacc[j][2] * qs);
                float p11 = ex2f(sacc[j][3] * qs);
                l0 += p00 + p01;
                l1 += p10 + p11;
                __half2 h0 = __floats2half2_rn(p00, p01);
                __half2 h1 = __floats2half2_rn(p10, p11);
                pa[j][0] = *(uint32_t*)&h0;
                pa[j][1] = *(uint32_t*)&h1;
            }

            // ---- O += P V ----
#pragma unroll
            for (int c2 = 0; c2 < 2; c2++) {
                uint32_t a0 = pa[2 * c2][0], a1 = pa[2 * c2][1];
                uint32_t a2 = pa[2 * c2 + 1][0], a3 = pa[2 * c2 + 1][1];
#pragma unroll
                for (int jp = 0; jp < 4; jp++) {
                    uint32_t bf0, bf1, bf2, bf3;
                    uint32_t addr = smem_u32(&Vs[st][c2 * 16 + v_row_l][jp * 16 + v_col_l]);
                    LDSM_X4T(bf0, bf1, bf2, bf3, addr);
                    mma_f16(oacc[2 * jp][0], oacc[2 * jp][1], oacc[2 * jp][2], oacc[2 * jp][3],
                            a0, a1, a2, a3, bf0, bf1);
                    mma_f16(oacc[2 * jp + 1][0], oacc[2 * jp + 1][1],
                            oacc[2 * jp + 1][2], oacc[2 * jp + 1][3],
                            a0, a1, a2, a3, bf2, bf3);
                }
            }
            if (++st >= 3) st = 0;
        }

        // ---- finalize ----
        l0 += __shfl_xor_sync(0xffffffff, l0, 1);
        l0 += __shfl_xor_sync(0xffffffff, l0, 2);
        l1 += __shfl_xor_sync(0xffffffff, l1, 1);
        l1 += __shfl_xor_sync(0xffffffff, l1, 2);

        int row0 = q0 + wr + g;
        if (f == 1) {
            float inv0 = 1.0f / l0;
            float inv1 = 1.0f / l1;
            size_t b0 = (seqbase + row0) * DMODEL + col;
            size_t b1 = (seqbase + row0 + 8) * DMODEL + col;
#pragma unroll
            for (int j = 0; j < 8; j++) {
                int c2 = j * 8 + 2 * t;
                __half2 h0 = __floats2half2_rn(oacc[j][0] * inv0, oacc[j][1] * inv0);
                __half2 h1 = __floats2half2_rn(oacc[j][2] * inv1, oacc[j][3] * inv1);
                *(uint32_t*)&g_ctxh[b0 + c2] = *(uint32_t*)&h0;
                *(uint32_t*)&g_ctxh[b1 + c2] = *(uint32_t*)&h1;
            }
        } else {
            // unnormalized fp16 key-half partial + fp32 l-sums
            size_t base = ((size_t)(bz * HPS + h)) * (SEQ / 2);
            __half* Op = g_O2ph[kh];
#pragma unroll
            for (int j = 0; j < 8; j++) {
                int c2 = j * 8 + 2 * t;
                __half2 h0 = __floats2half2_rn(oacc[j][0], oacc[j][1]);
                __half2 h1 = __floats2half2_rn(oacc[j][2], oacc[j][3]);
                *(uint32_t*)&Op[(base + row0) * DK + c2] = *(uint32_t*)&h0;
                *(uint32_t*)&Op[(base + row0 + 8) * DK + c2] = *(uint32_t*)&h1;
            }
            if (t == 0) {
                g_l2[kh][base + row0]     = l0;
                g_l2[kh][base + row0 + 8] = l1;
            }
        }
    }
}

// ---------------------------------------------------------------------------
// Combine scale-2 key-half partials + upsample into ctx heads 8-15.
// O(i) = (P0(i)+P1(i)) / (l0(i)+l1(i)); then linear interp.
// ---------------------------------------------------------------------------
__global__ __launch_bounds__(256) void upsample_ctx()
{
    int idx = blockIdx.x * 256 + threadIdx.x;
    int d  = (idx & 15) * 4;
    int hh = (idx >> 4) & 7;
    int s  = (idx >> 7) & 2047;
    int b  = idx >> 18;

    const int L = SEQ / 2;
    float coord = (s + 0.5f) * 0.5f - 0.5f;
    coord = fmaxf(coord, 0.0f);
    int i0 = min((int)floorf(coord), L - 1);
    int i1 = min(i0 + 1, L - 1);
    float w = coord - (float)i0;

    size_t base = ((size_t)(b * HPS + hh)) * L;
    float linv0 = 1.0f / (g_l2[0][base + i0] + g_l2[1][base + i0]);
    float linv1 = 1.0f / (g_l2[0][base + i1] + g_l2[1][base + i1]);

    uint2 ua0 = *(const uint2*)&g_O2ph[0][(base + i0) * DK + d];
    uint2 ub0 = *(const uint2*)&g_O2ph[1][(base + i0) * DK + d];
    uint2 ua1 = *(const uint2*)&g_O2ph[0][(base + i1) * DK + d];
    uint2 ub1 = *(const uint2*)&g_O2ph[1][(base + i1) * DK + d];

    float2 a0l = __half22float2(*(__half2*)&ua0.x), a0h = __half22float2(*(__half2*)&ua0.y);
    float2 b0l = __half22float2(*(__half2*)&ub0.x), b0h = __half22float2(*(__half2*)&ub0.y);
    float2 a1l = __half22float2(*(__half2*)&ua1.x), a1h = __half22float2(*(__half2*)&ua1.y);
    float2 b1l = __half22float2(*(__half2*)&ub1.x), b1h = __half22float2(*(__half2*)&ub1.y);

    float v0x = (a0l.x + b0l.x) * linv0, v0y = (a0l.y + b0l.y) * linv0;
    float v0z = (a0h.x + b0h.x) * linv0, v0w = (a0h.y + b0h.y) * linv0;
    float v1x = (a1l.x + b1l.x) * linv1, v1y = (a1l.y + b1l.y) * linv1;
    float v1z = (a1h.x + b1h.x) * linv1, v1w = (a1h.y + b1h.y) * linv1;

    float x0 = v0x + (v1x - v0x) * w;
    float x1 = v0y + (v1y - v0y) * w;
    float x2 = v0z + (v1z - v0z) * w;
    float x3 = v0w + (v1w - v0w) * w;

    __half2 h01 = __floats2half2_rn(x0, x1);
    __half2 h23 = __floats2half2_rn(x2, x3);
    uint2 u;
    u.x = *(uint32_t*)&h01;
    u.y = *(uint32_t*)&h23;
    *(uint2*)&g_ctxh[((size_t)(b * SEQ + s)) * DMODEL + 512 + hh * DK + d] = u;
}

// ---------------------------------------------------------------------------
// kernel_launch
// ---------------------------------------------------------------------------
extern "C" void kernel_launch(void* const* d_in, const int* in_sizes, int n_in,
                              void* d_out, int out_size)
{
    const float* query = (const float*)d_in[0];
    const float* key   = (const float*)d_in[1];
    const float* value = (const float*)d_in[2];
    const float* w_q   = (const float*)d_in[3];
    const float* b_q   = (const float*)d_in[4];
    const float* w_k   = (const float*)d_in[5];
    const float* b_k   = (const float*)d_in[6];
    const float* w_v   = (const float*)d_in[7];
    const float* b_v   = (const float*)d_in[8];
    const float* w_o   = (const float*)d_in[9];
    const float* b_o   = (const float*)d_in[10];
    float* out = (float*)d_out;

    static int attr_done = 0;
    if (!attr_done) {
        cudaFuncSetAttribute(gemm_qkv, cudaFuncAttributeMaxDynamicSharedMemorySize, GEMM_SMEM);
        cudaFuncSetAttribute(gemm_out, cudaFuncAttributeMaxDynamicSharedMemorySize, GEMM_SMEM);
        attr_done = 1;
    }

    prepass<<<PRE_HALF / 256, 256>>>(query, key, value, w_q, w_k, w_v, w_o);

    gemm_qkv<<<dim3(2, 48, 3), 256, GEMM_SMEM>>>(b_q, b_k, b_v);

    flash_tc<<<296, 256>>>();

    upsample_ctx<<<2048, 256>>>();

    gemm_out<<<dim3(4, 32), 256, GEMM_SMEM>>>(b_o, out);
}

// round 16
// speedup vs baseline: 1.0877x; 1.0192x over previous
#include <cuda_runtime.h>
#include <cuda_fp16.h>
#include <cstdint>

// ---------------------------------------------------------------------------
// Problem constants
// ---------------------------------------------------------------------------
#define BATCH   2
#define SEQ     2048
#define DMODEL  1024
#define DK      64
#define HPS     8
#define MROWS   (BATCH * SEQ)        // 4096

// Row permutation (per batch): even seq positions -> [0,1024), odd -> [1024,2048).
#define PERM(s) (((s) >> 1) + (((s) & 1) << 10))
// inverse: source seq for permuted row d (within batch)
#define IPERM(d) ((((d) & 1023) << 1) | ((d) >> 10))

// ---------------------------------------------------------------------------
// Scratch
// ---------------------------------------------------------------------------
__device__ __align__(16) __half g_Qh[MROWS * DMODEL];
__device__ __align__(16) __half g_Kh[MROWS * DMODEL];
__device__ __align__(16) __half g_Vh[MROWS * DMODEL];
__device__ __align__(16) __half g_ctxh[MROWS * DMODEL];
// scale-2 attention: unnormalized key-half partials (fp16) + row l-sums (fp32)
__device__ __align__(16) __half g_O2ph[2][BATCH * HPS * (SEQ / 2) * DK];
__device__ float g_l2[2][BATCH * HPS * (SEQ / 2)];
__device__ int g_ctr;
// half copies of weights (inputs converted inside gemm_qkv via async staging)
__device__ __align__(16) __half g_wqh[DMODEL * DMODEL];
__device__ __align__(16) __half g_wkh[DMODEL * DMODEL];
__device__ __align__(16) __half g_wvh[DMODEL * DMODEL];
__device__ __align__(16) __half g_woh[DMODEL * DMODEL];

// ---------------------------------------------------------------------------
// Helpers
// ---------------------------------------------------------------------------
__device__ __forceinline__ uint32_t smem_u32(const void* p) {
    return (uint32_t)__cvta_generic_to_shared(p);
}
__device__ __forceinline__ void mma_f16(
    float& c0, float& c1, float& c2, float& c3,
    uint32_t a0, uint32_t a1, uint32_t a2, uint32_t a3,
    uint32_t b0, uint32_t b1)
{
    asm volatile(
        "mma.sync.aligned.m16n8k16.row.col.f32.f16.f16.f32 "
        "{%0,%1,%2,%3}, {%4,%5,%6,%7}, {%8,%9}, {%0,%1,%2,%3};"
        : "+f"(c0), "+f"(c1), "+f"(c2), "+f"(c3)
        : "r"(a0), "r"(a1), "r"(a2), "r"(a3), "r"(b0), "r"(b1));
}
#define LDSM_X4(r0, r1, r2, r3, addr) \
    asm volatile("ldmatrix.sync.aligned.m8n8.x4.shared.b16 {%0,%1,%2,%3}, [%4];" \
                 : "=r"(r0), "=r"(r1), "=r"(r2), "=r"(r3) : "r"(addr))
#define LDSM_X4T(r0, r1, r2, r3, addr) \
    asm volatile("ldmatrix.sync.aligned.m8n8.x4.trans.shared.b16 {%0,%1,%2,%3}, [%4];" \
                 : "=r"(r0), "=r"(r1), "=r"(r2), "=r"(r3) : "r"(addr))

__device__ __forceinline__ void cpa16(const void* sdst, const void* g) {
    uint32_t s = smem_u32(sdst);
    asm volatile("cp.async.cg.shared.global [%0], [%1], 16;" :: "r"(s), "l"(g));
}
__device__ __forceinline__ void cpa_commit() {
    asm volatile("cp.async.commit_group;");
}
template <int N>
__device__ __forceinline__ void cpa_wait() {
    asm volatile("cp.async.wait_group %0;" :: "n"(N));
}

// MUFU exp2 (off the FMA pipe).
__device__ __forceinline__ float ex2f(float y) {
    float r;
    asm("ex2.approx.f32 %0, %1;" : "=f"(r) : "f"(y));
    return r;
}

// ---------------------------------------------------------------------------
// Prepass: weights fp32 -> fp16 only (24MB). Resets the flash work counter.
// ---------------------------------------------------------------------------
__global__ __launch_bounds__(256) void prepass_w(
    const float* __restrict__ wq, const float* __restrict__ wk,
    const float* __restrict__ wv, const float* __restrict__ wo)
{
    if (blockIdx.x == 0 && threadIdx.x == 0) g_ctr = 0;
    size_t i4 = (size_t)blockIdx.x * 256 + threadIdx.x;   // 0..1048575
    size_t a = i4 >> 18;
    size_t off = (i4 & 262143u) << 2;
    const float* s = (a == 0) ? wq : (a == 1) ? wk : (a == 2) ? wv : wo;
    __half* d = (a == 0) ? g_wqh : (a == 1) ? g_wkh : (a == 2) ? g_wvh : g_woh;
    float4 x = *(const float4*)&s[off];
    __half2 h01 = __floats2half2_rn(x.x, x.y);
    __half2 h23 = __floats2half2_rn(x.z, x.w);
    uint2 u;
    u.x = *(uint32_t*)&h01;
    u.y = *(uint32_t*)&h23;
    *(uint2*)&d[off] = u;
}

// ---------------------------------------------------------------------------
// GEMM common: 128x256 tile, BK=32, 256 thr (8 warps, 2m x 4n, warp 64x64).
// fp16 A tile stride 40 halves; B tile stride 264 halves.
// ---------------------------------------------------------------------------
#define GBK 32
#define ASTR 40
#define BSTR 264
#define A_ST_BYTES (128 * ASTR * 2)      // 10240
#define B_ST_BYTES (GBK * BSTR * 2)      // 16896
#define A_TOT (4 * A_ST_BYTES)
#define OUT_SMEM (A_TOT + 4 * B_ST_BYTES)        // gemm_out: 108544

// gemm_qkv smem: fp32 A stages + fp16 A double buffer + B stages
#define A32STR 36                                 // floats per A32 row
#define A32_ST_BYTES (128 * A32STR * 4)           // 18432
#define A32_TOT (4 * A32_ST_BYTES)                // 73728
#define A16_TOT (2 * A_ST_BYTES)                  // 20480
#define QKV_SMEM (A32_TOT + A16_TOT + 4 * B_ST_BYTES)   // 161792

__device__ __forceinline__ void issueB(
    char* Bs, const __half* __restrict__ W, int bcol, int k0, int tid)
{
#pragma unroll
    for (int r = 0; r < 4; r++) {
        int c = tid + r * 256;
        int brw = c >> 5, bch = (c & 31) << 3;
        cpa16(Bs + brw * (BSTR * 2) + bch * 2,
              &W[(size_t)(k0 + brw) * DMODEL + bcol + bch]);
    }
}

// Compute from explicit fp16 A tile / B tile pointers.
#define GEMM_COMPUTE(As_, Bs_)                                                 \
    do {                                                                       \
        _Pragma("unroll")                                                      \
        for (int kc = 0; kc < GBK; kc += 16) {                                 \
            uint32_t af[4][4];                                                 \
            _Pragma("unroll")                                                  \
            for (int i = 0; i < 4; i++) {                                      \
                uint32_t addr = smem_u32((As_) + (wm + 16 * i + a_row_l) * (ASTR * 2) \
                                                + (kc + a_k_l) * 2);           \
                LDSM_X4(af[i][0], af[i][1], af[i][2], af[i][3], addr);         \
            }                                                                  \
            uint32_t bf[8][2];                                                 \
            _Pragma("unroll")                                                  \
            for (int jp = 0; jp < 4; jp++) {                                   \
                uint32_t addr = smem_u32((Bs_) + (kc + b_row_l) * (BSTR * 2)   \
                                                + (wn + jp * 16 + b_col_l) * 2); \
                LDSM_X4T(bf[jp * 2][0], bf[jp * 2][1],                         \
                         bf[jp * 2 + 1][0], bf[jp * 2 + 1][1], addr);          \
            }                                                                  \
            _Pragma("unroll")                                                  \
            for (int i = 0; i < 4; i++)                                        \
                _Pragma("unroll")                                              \
                for (int j = 0; j < 8; j++)                                    \
                    mma_f16(c[i][j][0], c[i][j][1], c[i][j][2], c[i][j][3],    \
                            af[i][0], af[i][1], af[i][2], af[i][3],            \
                            bf[j][0], bf[j][1]);                               \
        }                                                                      \
    } while (0)

// ---------------------------------------------------------------------------
// gemm_qkv: A = ORIGINAL fp32 inputs, staged via cp.async into fp32 smem
// (4 stages, 3 iters ahead — async, unlike the R14 sync-LDG regression),
// converted smem->smem into a fp16 double buffer feeding ldmatrix.
// Grid (2, 48, 3): by<32 full row blocks cols 0-511; by>=32 even rows, 512+.
// ---------------------------------------------------------------------------
__global__ __launch_bounds__(256, 1) void gemm_qkv(
    const float* __restrict__ q, const float* __restrict__ k,
    const float* __restrict__ v,
    const float* __restrict__ bq, const float* __restrict__ bk,
    const float* __restrict__ bv)
{
    int z = blockIdx.z;
    const float* Af = (z == 0) ? q : (z == 1) ? k : v;
    const __half* W = (z == 0) ? g_wqh : (z == 1) ? g_wkh : g_wvh;
    const float* bias = (z == 0) ? bq : (z == 1) ? bk : bv;
    __half* C = (z == 0) ? g_Qh : (z == 1) ? g_Kh : g_Vh;

    int bcol, by;
    if (blockIdx.y < 32) { by = blockIdx.y; bcol = blockIdx.x * 256; }
    else {
        int rb = blockIdx.y - 32;
        by = (rb < 8) ? rb : rb + 8;
        bcol = 512 + blockIdx.x * 256;
    }
    const int brow = by * 128;

    extern __shared__ __align__(16) char dsm[];
    char* A32  = dsm;
    char* A16  = dsm + A32_TOT;
    char* Bb   = dsm + A32_TOT + A16_TOT;

    const int tid  = threadIdx.x;
    const int warp = tid >> 5;
    const int lane = tid & 31;
    const int g = lane >> 2;
    const int t = lane & 3;
    const int wm = (warp >> 2) * 64;
    const int wn = (warp & 3) * 64;

    // ---- A32 loader: 4 rows/thread, 4 floats each ----
    const int l_row0 = tid >> 3;          // 0..31
    const int l_c4   = (tid & 7) << 2;    // float col 0..28
    const float* asrc[4];
#pragma unroll
    for (int r = 0; r < 4; r++) {
        int row = l_row0 + r * 32;
        int R = brow + row;
        int bb = R >> 11, rq = R & 2047;
        asrc[r] = Af + (size_t)(bb * 2048 + IPERM(rq)) * DMODEL + l_c4;
    }
    auto issueA32 = [&](int st, int k0) {
        char* As = A32 + st * A32_ST_BYTES;
#pragma unroll
        for (int r = 0; r < 4; r++) {
            int row = l_row0 + r * 32;
            cpa16(As + (row * A32STR + l_c4) * 4, asrc[r] + k0);
        }
    };

    // ---- converter: 1 row / thread-pair, 16 floats ----
    const int cv_row = tid >> 1;
    const int cv_h   = (tid & 1) * 16;    // float col base
    auto convertA = [&](int st, int buf) {
        const float* src = (const float*)(A32 + st * A32_ST_BYTES)
                         + cv_row * A32STR + cv_h;
        char* dst = A16 + buf * A_ST_BYTES + (cv_row * ASTR + cv_h) * 2;
        float4 f0 = ((const float4*)src)[0];
        float4 f1 = ((const float4*)src)[1];
        float4 f2 = ((const float4*)src)[2];
        float4 f3 = ((const float4*)src)[3];
        __half2 p0 = __floats2half2_rn(f0.x, f0.y);
        __half2 p1 = __floats2half2_rn(f0.z, f0.w);
        __half2 p2 = __floats2half2_rn(f1.x, f1.y);
        __half2 p3 = __floats2half2_rn(f1.z, f1.w);
        __half2 p4 = __floats2half2_rn(f2.x, f2.y);
        __half2 p5 = __floats2half2_rn(f2.z, f2.w);
        __half2 p6 = __floats2half2_rn(f3.x, f3.y);
        __half2 p7 = __floats2half2_rn(f3.z, f3.w);
        uint4 u0 = make_uint4(*(uint32_t*)&p0, *(uint32_t*)&p1,
                              *(uint32_t*)&p2, *(uint32_t*)&p3);
        uint4 u1 = make_uint4(*(uint32_t*)&p4, *(uint32_t*)&p5,
                              *(uint32_t*)&p6, *(uint32_t*)&p7);
        *(uint4*)dst        = u0;
        *(uint4*)(dst + 16) = u1;
    };

    float c[4][8][4];
#pragma unroll
    for (int i = 0; i < 4; i++)
#pragma unroll
        for (int j = 0; j < 8; j++)
#pragma unroll
            for (int r = 0; r < 4; r++) c[i][j][r] = 0.0f;

    // ---- prologue: stages 0,1,2 ----
    issueA32(0, 0);        issueB(Bb,                 W, bcol, 0,        tid); cpa_commit();
    issueA32(1, GBK);      issueB(Bb + B_ST_BYTES,    W, bcol, GBK,      tid); cpa_commit();
    issueA32(2, 2 * GBK);  issueB(Bb + 2 * B_ST_BYTES,W, bcol, 2 * GBK,  tid); cpa_commit();

    const int a_row_l = lane & 15;
    const int a_k_l   = (lane >> 4) << 3;
    const int b_row_l = (lane & 7) + (((lane >> 3) & 1) << 3);
    const int b_col_l = (lane >> 4) << 3;

    const int NIT = DMODEL / GBK;   // 32
    for (int it = 0; it < NIT; it++) {
        const int st = it & 3;
        cpa_wait<2>();
        __syncthreads();               // stage st (A32 + B) visible
        convertA(st, it & 1);
        if (it + 3 < NIT) {
            int st3 = (it + 3) & 3;
            issueA32(st3, (it + 3) * GBK);
            issueB(Bb + st3 * B_ST_BYTES, W, bcol, (it + 3) * GBK, tid);
        }
        cpa_commit();
        __syncthreads();               // A16[it&1] writes visible

        GEMM_COMPUTE(A16 + (it & 1) * A_ST_BYTES, Bb + st * B_ST_BYTES);
    }

    // ---- epilogue (fp16 out) ----
    float bj[8][2];
#pragma unroll
    for (int j = 0; j < 8; j++) {
        int col = bcol + wn + 8 * j + 2 * t;
        bj[j][0] = bias[col];
        bj[j][1] = bias[col + 1];
    }
#pragma unroll
    for (int i = 0; i < 4; i++) {
        int row0 = brow + wm + 16 * i + g;
#pragma unroll
        for (int j = 0; j < 8; j++) {
            int col = bcol + wn + 8 * j + 2 * t;
            __half2 h0 = __floats2half2_rn(c[i][j][0] + bj[j][0], c[i][j][1] + bj[j][1]);
            __half2 h1 = __floats2half2_rn(c[i][j][2] + bj[j][0], c[i][j][3] + bj[j][1]);
            *(uint32_t*)&C[(size_t)row0 * DMODEL + col] = *(uint32_t*)&h0;
            *(uint32_t*)&C[(size_t)(row0 + 8) * DMODEL + col] = *(uint32_t*)&h1;
        }
    }
}

// ---------------------------------------------------------------------------
// gemm_out: both operands fp16 (ctx + w_o), 4-stage cp.async, fp32 out.
// ---------------------------------------------------------------------------
__device__ __forceinline__ void issueA16(
    char* As, const __half* __restrict__ A, int brow, int k0, int tid)
{
#pragma unroll
    for (int r = 0; r < 2; r++) {
        int c = tid + r * 256;
        int ar = c >> 2, ach = (c & 3) << 3;
        cpa16(As + ar * (ASTR * 2) + ach * 2,
              &A[(size_t)(brow + ar) * DMODEL + k0 + ach]);
    }
}

__global__ __launch_bounds__(256, 1) void gemm_out(
    const float* __restrict__ bo, float* __restrict__ out)
{
    const __half* A = g_ctxh;
    const __half* W = g_woh;
    const int brow = blockIdx.y * 128;
    const int bcol = blockIdx.x * 256;

    extern __shared__ __align__(16) char dsm[];
    char* Ab = dsm;
    char* Bb = dsm + A_TOT;

    const int tid  = threadIdx.x;
    const int warp = tid >> 5;
    const int lane = tid & 31;
    const int g = lane >> 2;
    const int t = lane & 3;
    const int wm = (warp >> 2) * 64;
    const int wn = (warp & 3) * 64;

    float c[4][8][4];
#pragma unroll
    for (int i = 0; i < 4; i++)
#pragma unroll
        for (int j = 0; j < 8; j++)
#pragma unroll
            for (int r = 0; r < 4; r++) c[i][j][r] = 0.0f;

    issueA16(Ab, A, brow, 0, tid);
    issueB(Bb, W, bcol, 0, tid);                                cpa_commit();
    issueA16(Ab + A_ST_BYTES, A, brow, GBK, tid);
    issueB(Bb + B_ST_BYTES, W, bcol, GBK, tid);                 cpa_commit();
    issueA16(Ab + 2 * A_ST_BYTES, A, brow, 2 * GBK, tid);
    issueB(Bb + 2 * B_ST_BYTES, W, bcol, 2 * GBK, tid);         cpa_commit();

    const int a_row_l = lane & 15;
    const int a_k_l   = (lane >> 4) << 3;
    const int b_row_l = (lane & 7) + (((lane >> 3) & 1) << 3);
    const int b_col_l = (lane >> 4) << 3;

    const int NIT = DMODEL / GBK;
    for (int it = 0; it < NIT; it++) {
        const int st = it & 3;
        cpa_wait<2>();
        __syncthreads();
        if (it + 3 < NIT) {
            int st3 = (it + 3) & 3;
            issueA16(Ab + st3 * A_ST_BYTES, A, brow, (it + 3) * GBK, tid);
            issueB(Bb + st3 * B_ST_BYTES, W, bcol, (it + 3) * GBK, tid);
        }
        cpa_commit();

        GEMM_COMPUTE(Ab + st * A_ST_BYTES, Bb + st * B_ST_BYTES);
    }

    float bj[8][2];
#pragma unroll
    for (int j = 0; j < 8; j++) {
        int col = bcol + wn + 8 * j + 2 * t;
        bj[j][0] = bo[col];
        bj[j][1] = bo[col + 1];
    }
#pragma unroll
    for (int i = 0; i < 4; i++) {
        int row0 = brow + wm + 16 * i + g;
#pragma unroll
        for (int j = 0; j < 8; j++) {
            int col = bcol + wn + 8 * j + 2 * t;
            float2 v0 = make_float2(c[i][j][0] + bj[j][0], c[i][j][1] + bj[j][1]);
            float2 v1 = make_float2(c[i][j][2] + bj[j][0], c[i][j][3] + bj[j][1]);
            *(float2*)&out[(size_t)row0 * DMODEL + col] = v0;
            *(float2*)&out[(size_t)(row0 + 8) * DMODEL + col] = v1;
        }
    }
}

// ---------------------------------------------------------------------------
// Persistent FP16 flash attention. 296 CTAs x 256 thr, atomic work queue.
// Items 0..255:   scale1, 128q x 2048k (64 tiles); normalized, -> g_ctxh.
// Items 256..511: scale2, 128q x 512k key-half (16 tiles); UNNORMALIZED
//                 fp16 partial O + fp32 per-row l to g_O2ph/g_l2.
// ---------------------------------------------------------------------------
#define FKT 32
#define KVSTR 72
#define NITEMS 512

__global__ __launch_bounds__(256, 2) void flash_tc()
{
    __shared__ __align__(16) __half Ks[3][FKT][KVSTR];
    __shared__ __align__(16) __half Vs[3][FKT][KVSTR];
    __shared__ int s_item;

    const int tid  = threadIdx.x;
    const int warp = tid >> 5;
    const int lane = tid & 31;
    const int g = lane >> 2;
    const int t = lane & 3;
    const int wr = warp * 16;
    const int lrow = tid >> 3;
    const int lch  = (tid & 7) << 3;

    const int kn_row_l = (lane & 7) + (((lane >> 4) & 1) << 3);
    const int kn_col_l = ((lane >> 3) & 1) << 3;
    const int v_row_l  = (lane & 7) + (((lane >> 3) & 1) << 3);
    const int v_col_l  = (lane >> 4) << 3;
    const float qs = 0.125f * 1.4426950408889634f;

    for (;;) {
        if (tid == 0) s_item = atomicAdd(&g_ctr, 1);
        __syncthreads();
        const int item = s_item;
        __syncthreads();
        if (item >= NITEMS) break;

        int f, head_off, qblk, bz, h, kh, ntiles;
        if (item < 256) {
            f = 1; head_off = 0; kh = 0; ntiles = 64;
            bz = item >> 7; h = (item >> 4) & 7; qblk = item & 15;
        } else {
            int j = item - 256;
            f = 2; head_off = HPS; ntiles = 16;
            kh = j & 1;
            int jj = j >> 1;
            bz = jj >> 6; h = (jj >> 3) & 7; qblk = jj & 7;
        }
        const int col = (head_off + h) * DK;
        const int q0  = qblk * 128;
        const int tbase = kh * 16;
        const size_t seqbase = (size_t)bz * SEQ;

        // ---- Q fragments (permuted rows) ----
        uint32_t qf[4][4];
        {
            int sq0 = (q0 + wr + g) * f;
            int sq1 = sq0 + 8 * f;
            size_t r0 = (seqbase + PERM(sq0)) * DMODEL + col;
            size_t r1 = (seqbase + PERM(sq1)) * DMODEL + col;
#pragma unroll
            for (int kc = 0; kc < 4; kc++) {
                qf[kc][0] = *(const uint32_t*)&g_Qh[r0 + kc * 16 + 2 * t];
                qf[kc][1] = *(const uint32_t*)&g_Qh[r1 + kc * 16 + 2 * t];
                qf[kc][2] = *(const uint32_t*)&g_Qh[r0 + kc * 16 + 2 * t + 8];
                qf[kc][3] = *(const uint32_t*)&g_Qh[r1 + kc * 16 + 2 * t + 8];
            }
        }

        float oacc[8][4];
#pragma unroll
        for (int j = 0; j < 8; j++)
#pragma unroll
            for (int r = 0; r < 4; r++) oacc[j][r] = 0.0f;
        float l0 = 0.0f, l1 = 0.0f;

        auto issue = [&](int tile, int buf) {
            int sk = ((tbase + tile) * FKT + lrow) * f;
            size_t src = (seqbase + PERM(sk)) * DMODEL + col + lch;
            cpa16(&Ks[buf][lrow][lch], &g_Kh[src]);
            cpa16(&Vs[buf][lrow][lch], &g_Vh[src]);
        };

        issue(0, 0);
        cpa_commit();
        issue(1, 1);
        cpa_commit();

        int st = 0;
        for (int kt = 0; kt < ntiles; kt++) {
            cpa_wait<1>();
            __syncthreads();
            if (kt + 2 < ntiles) {
                int st2 = st + 2; if (st2 >= 3) st2 -= 3;
                issue(kt + 2, st2);
            }
            cpa_commit();

            // ---- S = Q K^T ----
            float sacc[4][4];
#pragma unroll
            for (int j = 0; j < 4; j++)
#pragma unroll
                for (int r = 0; r < 4; r++) sacc[j][r] = 0.0f;
#pragma unroll
            for (int kc = 0; kc < 4; kc++) {
                uint32_t bf[4][2];
#pragma unroll
                for (int jp = 0; jp < 2; jp++) {
                    uint32_t addr = smem_u32(&Ks[st][jp * 16 + kn_row_l][kc * 16 + kn_col_l]);
                    LDSM_X4(bf[jp * 2][0], bf[jp * 2][1],
                            bf[jp * 2 + 1][0], bf[jp * 2 + 1][1], addr);
                }
#pragma unroll
                for (int j = 0; j < 4; j++)
                    mma_f16(sacc[j][0], sacc[j][1], sacc[j][2], sacc[j][3],
                            qf[kc][0], qf[kc][1], qf[kc][2], qf[kc][3],
                            bf[j][0], bf[j][1]);
            }

            // ---- P = exp2(S*qs) via MUFU, straight into A fragments ----
            uint32_t pa[4][2];
#pragma unroll
            for (int j = 0; j < 4; j++) {
                float p00 = ex2f(sacc[j][0] * qs);
                float p01 = ex2f(sacc[j][1] * qs);
                float p10 = ex2f(sacc[j][2] * qs);
                float p11 = ex2f(sacc[j][3] * qs);
                l0 += p00 + p01;
                l1 += p10 + p11;
                __half2 h0 = __floats2half2_rn(p00, p01);
                __half2 h1 = __floats2half2_rn(p10, p11);
                pa[j][0] = *(uint32_t*)&h0;
                pa[j][1] = *(uint32_t*)&h1;
            }

            // ---- O += P V ----
#pragma unroll
            for (int c2 = 0; c2 < 2; c2++) {
                uint32_t a0 = pa[2 * c2][0], a1 = pa[2 * c2][1];
                uint32_t a2 = pa[2 * c2 + 1][0], a3 = pa[2 * c2 + 1][1];
#pragma unroll
                for (int jp = 0; jp < 4; jp++) {
                    uint32_t bf0, bf1, bf2, bf3;
                    uint32_t addr = smem_u32(&Vs[st][c2 * 16 + v_row_l][jp * 16 + v_col_l]);
                    LDSM_X4T(bf0, bf1, bf2, bf3, addr);
                    mma_f16(oacc[2 * jp][0], oacc[2 * jp][1], oacc[2 * jp][2], oacc[2 * jp][3],
                            a0, a1, a2, a3, bf0, bf1);
                    mma_f16(oacc[2 * jp + 1][0], oacc[2 * jp + 1][1],
                            oacc[2 * jp + 1][2], oacc[2 * jp + 1][3],
                            a0, a1, a2, a3, bf2, bf3);
                }
            }
            if (++st >= 3) st = 0;
        }

        // ---- finalize ----
        l0 += __shfl_xor_sync(0xffffffff, l0, 1);
        l0 += __shfl_xor_sync(0xffffffff, l0, 2);
        l1 += __shfl_xor_sync(0xffffffff, l1, 1);
        l1 += __shfl_xor_sync(0xffffffff, l1, 2);

        int row0 = q0 + wr + g;
        if (f == 1) {
            float inv0 = 1.0f / l0;
            float inv1 = 1.0f / l1;
            size_t b0 = (seqbase + row0) * DMODEL + col;
            size_t b1 = (seqbase + row0 + 8) * DMODEL + col;
#pragma unroll
            for (int j = 0; j < 8; j++) {
                int c2 = j * 8 + 2 * t;
                __half2 h0 = __floats2half2_rn(oacc[j][0] * inv0, oacc[j][1] * inv0);
                __half2 h1 = __floats2half2_rn(oacc[j][2] * inv1, oacc[j][3] * inv1);
                *(uint32_t*)&g_ctxh[b0 + c2] = *(uint32_t*)&h0;
                *(uint32_t*)&g_ctxh[b1 + c2] = *(uint32_t*)&h1;
            }
        } else {
            size_t base = ((size_t)(bz * HPS + h)) * (SEQ / 2);
            __half* Op = g_O2ph[kh];
#pragma unroll
            for (int j = 0; j < 8; j++) {
                int c2 = j * 8 + 2 * t;
                __half2 h0 = __floats2half2_rn(oacc[j][0], oacc[j][1]);
                __half2 h1 = __floats2half2_rn(oacc[j][2], oacc[j][3]);
                *(uint32_t*)&Op[(base + row0) * DK + c2] = *(uint32_t*)&h0;
                *(uint32_t*)&Op[(base + row0 + 8) * DK + c2] = *(uint32_t*)&h1;
            }
            if (t == 0) {
                g_l2[kh][base + row0]     = l0;
                g_l2[kh][base + row0 + 8] = l1;
            }
        }
    }
}

// ---------------------------------------------------------------------------
// Combine scale-2 key-half partials + upsample into ctx heads 8-15.
// ---------------------------------------------------------------------------
__global__ __launch_bounds__(256) void upsample_ctx()
{
    int idx = blockIdx.x * 256 + threadIdx.x;
    int d  = (idx & 15) * 4;
    int hh = (idx >> 4) & 7;
    int s  = (idx >> 7) & 2047;
    int b  = idx >> 18;

    const int L = SEQ / 2;
    float coord = (s + 0.5f) * 0.5f - 0.5f;
    coord = fmaxf(coord, 0.0f);
    int i0 = min((int)floorf(coord), L - 1);
    int i1 = min(i0 + 1, L - 1);
    float w = coord - (float)i0;

    size_t base = ((size_t)(b * HPS + hh)) * L;
    float linv0 = 1.0f / (g_l2[0][base + i0] + g_l2[1][base + i0]);
    float linv1 = 1.0f / (g_l2[0][base + i1] + g_l2[1][base + i1]);

    uint2 ua0 = *(const uint2*)&g_O2ph[0][(base + i0) * DK + d];
    uint2 ub0 = *(const uint2*)&g_O2ph[1][(base + i0) * DK + d];
    uint2 ua1 = *(const uint2*)&g_O2ph[0][(base + i1) * DK + d];
    uint2 ub1 = *(const uint2*)&g_O2ph[1][(base + i1) * DK + d];

    float2 a0l = __half22float2(*(__half2*)&ua0.x), a0h = __half22float2(*(__half2*)&ua0.y);
    float2 b0l = __half22float2(*(__half2*)&ub0.x), b0h = __half22float2(*(__half2*)&ub0.y);
    float2 a1l = __half22float2(*(__half2*)&ua1.x), a1h = __half22float2(*(__half2*)&ua1.y);
    float2 b1l = __half22float2(*(__half2*)&ub1.x), b1h = __half22float2(*(__half2*)&ub1.y);

    float v0x = (a0l.x + b0l.x) * linv0, v0y = (a0l.y + b0l.y) * linv0;
    float v0z = (a0h.x + b0h.x) * linv0, v0w = (a0h.y + b0h.y) * linv0;
    float v1x = (a1l.x + b1l.x) * linv1, v1y = (a1l.y + b1l.y) * linv1;
    float v1z = (a1h.x + b1h.x) * linv1, v1w = (a1h.y + b1h.y) * linv1;

    float x0 = v0x + (v1x - v0x) * w;
    float x1 = v0y + (v1y - v0y) * w;
    float x2 = v0z + (v1z - v0z) * w;
    float x3 = v0w + (v1w - v0w) * w;

    __half2 h01 = __floats2half2_rn(x0, x1);
    __half2 h23 = __floats2half2_rn(x2, x3);
    uint2 u;
    u.x = *(uint32_t*)&h01;
    u.y = *(uint32_t*)&h23;
    *(uint2*)&g_ctxh[((size_t)(b * SEQ + s)) * DMODEL + 512 + hh * DK + d] = u;
}

// ---------------------------------------------------------------------------
// kernel_launch
// ---------------------------------------------------------------------------
extern "C" void kernel_launch(void* const* d_in, const int* in_sizes, int n_in,
                              void* d_out, int out_size)
{
    const float* query = (const float*)d_in[0];
    const float* key   = (const float*)d_in[1];
    const float* value = (const float*)d_in[2];
    const float* w_q   = (const float*)d_in[3];
    const float* b_q   = (const float*)d_in[4];
    const float* w_k   = (const float*)d_in[5];
    const float* b_k   = (const float*)d_in[6];
    const float* w_v   = (const float*)d_in[7];
    const float* b_v   = (const float*)d_in[8];
    const float* w_o   = (const float*)d_in[9];
    const float* b_o   = (const float*)d_in[10];
    float* out = (float*)d_out;

    static int attr_done = 0;
    if (!attr_done) {
        cudaFuncSetAttribute(gemm_qkv, cudaFuncAttributeMaxDynamicSharedMemorySize, QKV_SMEM);
        cudaFuncSetAttribute(gemm_out, cudaFuncAttributeMaxDynamicSharedMemorySize, OUT_SMEM);
        attr_done = 1;
    }

    prepass_w<<<4096, 256>>>(w_q, w_k, w_v, w_o);

    gemm_qkv<<<dim3(2, 48, 3), 256, QKV_SMEM>>>(query, key, value, b_q, b_k, b_v);

    flash_tc<<<296, 256>>>();

    upsample_ctx<<<2048, 256>>>();

    gemm_out<<<dim3(4, 32), 256, OUT_SMEM>>>(b_o, out);
}